// round 8
// baseline (speedup 1.0000x reference)
#include <cuda_runtime.h>

#define NB 8
#define NC 512
#define NL 1024
#define NH 8
#define ND 64
#define GC 64
#define LTILE 128

typedef unsigned long long u64;
typedef unsigned int u32;

// ---------------- scratch (allocation-free rule) ---------------------------
__device__ float g_qt[NB*NH*NL*ND];   // Q conv out, [bh][l][d]  (transposed)
__device__ float g_kt[NB*NH*NL*ND];   // K conv out, [bh][m][d]  (transposed)
__device__ float g_vh[NB*NH*ND*NL];   // V conv out, [bh][d][m]  (d-major)
__device__ float g_o [NB*NL*NC];      // attention output, [b][l][c]

// ---------------- f32x2 helpers (conv) -------------------------------------
__device__ __forceinline__ u64 pk2(float lo, float hi) {
    u64 r; asm("mov.b64 %0, {%1, %2};" : "=l"(r) : "f"(lo), "f"(hi)); return r;
}
__device__ __forceinline__ void upk2(float& lo, float& hi, u64 v) {
    asm("mov.b64 {%0, %1}, %2;" : "=f"(lo), "=f"(hi) : "l"(v));
}
__device__ __forceinline__ u64 fma2(u64 a, u64 b, u64 c) {
    u64 d; asm("fma.rn.f32x2 %0, %1, %2, %3;" : "=l"(d) : "l"(a), "l"(b), "l"(c)); return d;
}

// ---------------- tensor helpers (legacy mma.sync on sm_103) ---------------
__device__ __forceinline__ float tf32hi(float x) {
    u32 r; asm("cvt.rna.tf32.f32 %0, %1;" : "=r"(r) : "f"(x));
    return __uint_as_float(r);
}
__device__ __forceinline__ void mma8(float d[4], const u32 a[4], u32 b0, u32 b1) {
    asm volatile("mma.sync.aligned.m16n8k8.row.col.f32.tf32.tf32.f32 "
        "{%0,%1,%2,%3}, {%4,%5,%6,%7}, {%8,%9}, {%0,%1,%2,%3};"
        : "+f"(d[0]), "+f"(d[1]), "+f"(d[2]), "+f"(d[3])
        : "r"(a[0]), "r"(a[1]), "r"(a[2]), "r"(a[3]), "r"(b0), "r"(b1));
}

// ---------------------------------------------------------------------------
// Grouped Conv1d (unchanged — f32x2 path)
// ---------------------------------------------------------------------------
__global__ __launch_bounds__(256, 2)
void conv_kernel(const float* __restrict__ x, const float* __restrict__ w, int which)
{
    __shared__ __align__(16) float xs [GC][LTILE+2];
    __shared__ float xt2[GC][LTILE+1];

    int bg = blockIdx.y;
    int b  = bg >> 3, g = bg & 7;
    int lt = blockIdx.x * LTILE;
    int tid = threadIdx.x;

    const float* xg = x + (size_t)(b*NC + g*GC) * NL;
    for (int i = tid; i < GC*(LTILE+2); i += 256) {
        int ch = i / (LTILE+2);
        int lo = i - ch*(LTILE+2);
        int lp = lt - 1 + lo;
        lp = (lp < 0) ? 1 : ((lp >= NL) ? (2*NL - 2 - lp) : lp);  // reflect
        xs[ch][lo] = xg[ch*NL + lp];
    }
    __syncthreads();

    int c  = tid >> 2;
    int lq = tid & 3;
    const float* wc = w + (size_t)(g*GC + c) * 192;

    u64 acc2[4][4];
    #pragma unroll
    for (int rp = 0; rp < 4; ++rp)
        #pragma unroll
        for (int j = 0; j < 4; ++j) acc2[rp][j] = 0ull;

    #pragma unroll 4
    for (int i = 0; i < GC; ++i) {
        float w0 = wc[i*3+0], w1 = wc[i*3+1], w2 = wc[i*3+2];
        u64 w00 = pk2(w0, w0), w11 = pk2(w1, w1), w22 = pk2(w2, w2);
        #pragma unroll
        for (int rp = 0; rp < 4; ++rp) {
            int l0 = rp*32 + lq*8;
            float xr[10];
            #pragma unroll
            for (int r = 0; r < 10; ++r) xr[r] = xs[i][l0 + r];
            u64 E[5], O[4];
            #pragma unroll
            for (int j = 0; j < 5; ++j) E[j] = pk2(xr[2*j],   xr[2*j+1]);
            #pragma unroll
            for (int j = 0; j < 4; ++j) O[j] = pk2(xr[2*j+1], xr[2*j+2]);
            #pragma unroll
            for (int j = 0; j < 4; ++j) {
                acc2[rp][j] = fma2(w00, E[j],   acc2[rp][j]);
                acc2[rp][j] = fma2(w11, O[j],   acc2[rp][j]);
                acc2[rp][j] = fma2(w22, E[j+1], acc2[rp][j]);
            }
        }
    }

    if (which == 2) {
        float* og = g_vh + (size_t)(bg*GC + c) * NL + lt;
        #pragma unroll
        for (int rp = 0; rp < 4; ++rp) {
            int l0 = rp*32 + lq*8;
            float a0,a1,a2v,a3,a4,a5,a6,a7;
            upk2(a0,a1, acc2[rp][0]); upk2(a2v,a3, acc2[rp][1]);
            upk2(a4,a5, acc2[rp][2]); upk2(a6,a7, acc2[rp][3]);
            *(float4*)(og + l0)     = make_float4(a0,a1,a2v,a3);
            *(float4*)(og + l0 + 4) = make_float4(a4,a5,a6,a7);
        }
    } else {
        #pragma unroll
        for (int rp = 0; rp < 4; ++rp) {
            int l0 = rp*32 + lq*8;
            float a0,a1,a2v,a3,a4,a5,a6,a7;
            upk2(a0,a1, acc2[rp][0]); upk2(a2v,a3, acc2[rp][1]);
            upk2(a4,a5, acc2[rp][2]); upk2(a6,a7, acc2[rp][3]);
            xt2[c][l0+0]=a0; xt2[c][l0+1]=a1; xt2[c][l0+2]=a2v; xt2[c][l0+3]=a3;
            xt2[c][l0+4]=a4; xt2[c][l0+5]=a5; xt2[c][l0+6]=a6;  xt2[c][l0+7]=a7;
        }
        __syncthreads();
        float* base_t = ((which == 0) ? g_qt : g_kt) + (size_t)bg * NL * ND;
        #pragma unroll
        for (int it = 0; it < 8; ++it) {
            int fid = it*256 + tid;
            int l = fid >> 4, d4 = fid & 15;
            float4 v = make_float4(xt2[4*d4+0][l], xt2[4*d4+1][l],
                                   xt2[4*d4+2][l], xt2[4*d4+3][l]);
            *(float4*)(base_t + (size_t)(lt + l)*ND + 4*d4) = v;
        }
    }
}

// ---------------------------------------------------------------------------
// Causal attention: mma.sync m16n8k8 tf32 (x3 compensated).
// R6 skeleton (Q frags in regs, ktile 64, 8 warps) + frag-packed K/V smem:
// each B fragment for all 3 compensated MMAs = ONE LDS.128.
// Packed element: {hi(c), hi(c+4), lo(c), lo(c+4)} at [row][k][q4].
// Q pre-scaled by 1/sqrt(8); exp-direct softmax (scores bounded, fp32-safe).
// ---------------------------------------------------------------------------
#define KP_PITCH 36    // float4 per packed row (8k * 4q4 = 32, pad -> 36)
#define SM_QS_BYTES (128*68*4)                 // 34,816
#define SM_KP_BYTES (64*KP_PITCH*16)           // 36,864
#define SMEM_ATTN (SM_QS_BYTES + 2*SM_KP_BYTES)  // 108,544

__global__ __launch_bounds__(256, 1)
void attn_kernel()
{
    extern __shared__ __align__(16) char smraw[];
    float*  Qs = (float*) smraw;
    float4* Kp = (float4*)(smraw + SM_QS_BYTES);
    float4* Vp = (float4*)(smraw + SM_QS_BYTES + SM_KP_BYTES);

    int tid  = threadIdx.x;
    int w    = tid >> 5;
    int lane = tid & 31;
    int g    = lane >> 2;
    int q4   = lane & 3;
    int bh   = blockIdx.y;
    int qt   = 7 - blockIdx.x;     // heavy q-tiles first
    int row0 = qt * 128;

    const float* Qg = g_qt + (size_t)bh * NL * ND + (size_t)row0 * ND;
    const float* Kg = g_kt + (size_t)bh * NL * ND;
    const float* Vg = g_vh + (size_t)bh * ND * NL;

    const float scale = 0.35355339059327373f;   // 1/sqrt(8), folded into Q

    // ---- stage Q tile [128][64] (scaled) -> Qs ----
    #pragma unroll
    for (int it = 0; it < 8; ++it) {
        int fid = it*256 + tid;
        int l = fid >> 4, d4 = fid & 15;
        float4 v = *(const float4*)(Qg + (size_t)l*ND + 4*d4);
        *(float4*)(&Qs[l*68 + 4*d4]) =
            make_float4(v.x*scale, v.y*scale, v.z*scale, v.w*scale);
    }
    __syncthreads();

    // ---- Q fragments (hi/lo) -> registers, reused all key tiles ----
    u32 qAhi[8][4], qAlo[8][4];
    {
        int rbl = w*16 + g;
        #pragma unroll
        for (int k = 0; k < 8; ++k) {
            float f[4];
            f[0] = Qs[(rbl  )*68 + 8*k + q4];
            f[1] = Qs[(rbl+8)*68 + 8*k + q4];
            f[2] = Qs[(rbl  )*68 + 8*k + q4 + 4];
            f[3] = Qs[(rbl+8)*68 + 8*k + q4 + 4];
            #pragma unroll
            for (int e = 0; e < 4; ++e) {
                float h = tf32hi(f[e]);
                qAhi[k][e] = __float_as_uint(h);
                qAlo[k][e] = __float_as_uint(f[e] - h);
            }
        }
    }

    float oacc[8][4];
    #pragma unroll
    for (int n = 0; n < 8; ++n)
        #pragma unroll
        for (int e = 0; e < 4; ++e) oacc[n][e] = 0.f;
    float s0 = 0.f, s1 = 0.f;

    int rbase = row0 + w*16 + g;
    int nkt   = 2*qt + 2;          // 64-key tiles
    int src0  = (lane & ~3) | (q4 >> 1);
    int src1  = src0 + 2;

    for (int kt = 0; kt < nkt; ++kt) {
        __syncthreads();           // previous tile fully consumed
        // ---- stage K tile [64 keys][64 d] frag-packed ----
        #pragma unroll
        for (int it = 0; it < 2; ++it) {
            int u = it*256 + tid;           // 512 units
            int m = u >> 3, k = u & 7;
            const float* src = Kg + (size_t)(kt*64 + m)*ND + k*8;
            float4 v0 = *(const float4*)(src);
            float4 v1 = *(const float4*)(src + 4);
            float f[8] = {v0.x, v0.y, v0.z, v0.w, v1.x, v1.y, v1.z, v1.w};
            float h[8];
            #pragma unroll
            for (int e = 0; e < 8; ++e) h[e] = tf32hi(f[e]);
            float4* dst = Kp + m*KP_PITCH + k*4;
            #pragma unroll
            for (int j = 0; j < 4; ++j)
                dst[j] = make_float4(h[j], h[j+4], f[j]-h[j], f[j+4]-h[j+4]);
        }
        // ---- stage V tile [64 d][64 m] frag-packed ----
        #pragma unroll
        for (int it = 0; it < 2; ++it) {
            int u = it*256 + tid;
            int d = u >> 3, kk = u & 7;
            const float* src = Vg + (size_t)d*NL + kt*64 + kk*8;
            float4 v0 = *(const float4*)(src);
            float4 v1 = *(const float4*)(src + 4);
            float f[8] = {v0.x, v0.y, v0.z, v0.w, v1.x, v1.y, v1.z, v1.w};
            float h[8];
            #pragma unroll
            for (int e = 0; e < 8; ++e) h[e] = tf32hi(f[e]);
            float4* dst = Vp + d*KP_PITCH + kk*4;
            #pragma unroll
            for (int j = 0; j < 4; ++j)
                dst[j] = make_float4(h[j], h[j+4], f[j]-h[j], f[j+4]-h[j+4]);
        }
        __syncthreads();

        // ---- S = Q K^T (tf32x3), B frag = 1 LDS.128 ----
        float sc[8][4];
        #pragma unroll
        for (int n = 0; n < 8; ++n)
            #pragma unroll
            for (int e = 0; e < 4; ++e) sc[n][e] = 0.f;

        #pragma unroll
        for (int k = 0; k < 8; ++k) {
            #pragma unroll
            for (int n = 0; n < 8; ++n) {
                float4 bf = Kp[(8*n + g)*KP_PITCH + k*4 + q4];
                u32 bh0 = __float_as_uint(bf.x), bh1 = __float_as_uint(bf.y);
                u32 bl0 = __float_as_uint(bf.z), bl1 = __float_as_uint(bf.w);
                mma8(sc[n], qAhi[k], bh0, bh1);
                mma8(sc[n], qAlo[k], bh0, bh1);
                mma8(sc[n], qAhi[k], bl0, bl1);
            }
        }

        // ---- softmax: exp-direct + causal mask ----
        #pragma unroll
        for (int n = 0; n < 8; ++n) {
            int cbase = kt*64 + 8*n + 2*q4;
            #pragma unroll
            for (int e = 0; e < 4; ++e) {
                int r = rbase + ((e >> 1) << 3);
                int c = cbase + (e & 1);
                float p = (c > r) ? 0.f : __expf(sc[n][e]);
                sc[n][e] = p;
                if (e < 2) s0 += p; else s1 += p;
            }
        }

        // ---- O += P V^T (tf32x3); P acc->A frag via quad shuffles ----
        #pragma unroll
        for (int kk = 0; kk < 8; ++kk) {
            float v00 = __shfl_sync(0xffffffffu, sc[kk][0], src0);
            float v01 = __shfl_sync(0xffffffffu, sc[kk][1], src0);
            float v20 = __shfl_sync(0xffffffffu, sc[kk][2], src0);
            float v21 = __shfl_sync(0xffffffffu, sc[kk][3], src0);
            float w00 = __shfl_sync(0xffffffffu, sc[kk][0], src1);
            float w01 = __shfl_sync(0xffffffffu, sc[kk][1], src1);
            float w20 = __shfl_sync(0xffffffffu, sc[kk][2], src1);
            float w21 = __shfl_sync(0xffffffffu, sc[kk][3], src1);
            bool odd = (q4 & 1);
            float a[4];
            a[0] = odd ? v01 : v00;
            a[1] = odd ? v21 : v20;
            a[2] = odd ? w01 : w00;
            a[3] = odd ? w21 : w20;
            u32 pahi[4], palo[4];
            #pragma unroll
            for (int e = 0; e < 4; ++e) {
                float h = tf32hi(a[e]);
                pahi[e] = __float_as_uint(h);
                palo[e] = __float_as_uint(a[e] - h);
            }
            #pragma unroll
            for (int n = 0; n < 8; ++n) {
                float4 bf = Vp[(8*n + g)*KP_PITCH + kk*4 + q4];
                u32 bh0 = __float_as_uint(bf.x), bh1 = __float_as_uint(bf.y);
                u32 bl0 = __float_as_uint(bf.z), bl1 = __float_as_uint(bf.w);
                mma8(oacc[n], pahi, bh0, bh1);
                mma8(oacc[n], palo, bh0, bh1);
                mma8(oacc[n], pahi, bl0, bl1);
            }
        }
    }

    // ---- finalize: quad-reduce row sums, normalize, write ----
    s0 += __shfl_xor_sync(0xffffffffu, s0, 1);
    s0 += __shfl_xor_sync(0xffffffffu, s0, 2);
    s1 += __shfl_xor_sync(0xffffffffu, s1, 1);
    s1 += __shfl_xor_sync(0xffffffffu, s1, 2);
    float inv0 = 1.f / s0, inv1 = 1.f / s1;

    int b = bh >> 3, h = bh & 7;
    float* Ob0 = g_o + ((size_t)(b*NL + rbase    ))*NC + h*ND;
    float* Ob1 = g_o + ((size_t)(b*NL + rbase + 8))*NC + h*ND;
    #pragma unroll
    for (int n = 0; n < 8; ++n) {
        int d = 8*n + 2*q4;
        *(float2*)(Ob0 + d) = make_float2(oacc[n][0]*inv0, oacc[n][1]*inv0);
        *(float2*)(Ob1 + d) = make_float2(oacc[n][2]*inv1, oacc[n][3]*inv1);
    }
}

// ---------------------------------------------------------------------------
// Residual add + LayerNorm over channel, transposed-tile version (unchanged).
// ---------------------------------------------------------------------------
#define TL 16
__global__ __launch_bounds__(128)
void ln_kernel(const float* __restrict__ init, const float* __restrict__ gamma,
               const float* __restrict__ beta, float* __restrict__ y)
{
    __shared__ float xt[TL][NC + 4];

    int blk = blockIdx.x;
    int b   = blk >> 6;
    int lt  = (blk & 63) * TL;
    int tid = threadIdx.x;

    const float* ib = init + (size_t)b * NC * NL + lt;
    float*       yb = y    + (size_t)b * NC * NL + lt;

    for (int i = tid; i < NC * (TL/4); i += 128) {
        int c = i >> 2, j = i & 3;
        float4 v = *(const float4*)(ib + (size_t)c * NL + 4*j);
        xt[4*j+0][c] = v.x; xt[4*j+1][c] = v.y;
        xt[4*j+2][c] = v.z; xt[4*j+3][c] = v.w;
    }
    __syncthreads();

    int w = tid >> 5, lane = tid & 31;
    const float* ob_base = g_o + ((size_t)(b*NL + lt)) * NC;
    for (int r = w; r < TL; r += 4) {
        const float4* orow = (const float4*)(ob_base + (size_t)r * NC);
        float4 xv[4];
        float s1 = 0.f, s2 = 0.f;
        #pragma unroll
        for (int kk = 0; kk < 4; ++kk) {
            int c4 = lane + 32*kk;
            float4 ov = orow[c4];
            float4 iv = *(const float4*)(&xt[r][4*c4]);
            xv[kk] = make_float4(ov.x+iv.x, ov.y+iv.y, ov.z+iv.z, ov.w+iv.w);
            s1 += xv[kk].x + xv[kk].y + xv[kk].z + xv[kk].w;
            s2 += xv[kk].x*xv[kk].x + xv[kk].y*xv[kk].y
                + xv[kk].z*xv[kk].z + xv[kk].w*xv[kk].w;
        }
        #pragma unroll
        for (int off = 16; off; off >>= 1) {
            s1 += __shfl_xor_sync(0xffffffffu, s1, off);
            s2 += __shfl_xor_sync(0xffffffffu, s2, off);
        }
        float mu   = s1 * (1.f/512.f);
        float var  = s2 * (1.f/512.f) - mu*mu;
        float rstd = rsqrtf(var + 1e-5f);

        #pragma unroll
        for (int kk = 0; kk < 4; ++kk) {
            int c4 = lane + 32*kk;
            float4 gv = ((const float4*)gamma)[c4];
            float4 bv = ((const float4*)beta)[c4];
            float4 r4;
            r4.x = (xv[kk].x - mu)*rstd*gv.x + bv.x;
            r4.y = (xv[kk].y - mu)*rstd*gv.y + bv.y;
            r4.z = (xv[kk].z - mu)*rstd*gv.z + bv.z;
            r4.w = (xv[kk].w - mu)*rstd*gv.w + bv.w;
            *(float4*)(&xt[r][4*c4]) = r4;
        }
    }
    __syncthreads();

    for (int i = tid; i < NC * (TL/4); i += 128) {
        int c = i >> 2, j = i & 3;
        float4 v = make_float4(xt[4*j+0][c], xt[4*j+1][c],
                               xt[4*j+2][c], xt[4*j+3][c]);
        *(float4*)(yb + (size_t)c * NL + 4*j) = v;
    }
}

// ---------------------------------------------------------------------------
extern "C" void kernel_launch(void* const* d_in, const int* in_sizes, int n_in,
                              void* d_out, int out_size)
{
    const float* q     = (const float*)d_in[0];
    const float* k     = (const float*)d_in[1];
    // d_in[2] = mask — causal, handled analytically
    const float* wq    = (const float*)d_in[3];
    const float* wk    = (const float*)d_in[4];
    const float* wv    = (const float*)d_in[5];
    const float* gamma = (const float*)d_in[6];
    const float* beta  = (const float*)d_in[7];
    float* out = (float*)d_out;

    cudaFuncSetAttribute(attn_kernel,
                         cudaFuncAttributeMaxDynamicSharedMemorySize, SMEM_ATTN);

    dim3 cgrid(NL / LTILE, NB * NH);
    conv_kernel<<<cgrid, 256>>>(q, wq, 0);
    conv_kernel<<<cgrid, 256>>>(k, wk, 1);
    conv_kernel<<<cgrid, 256>>>(k, wv, 2);   // v = k

    attn_kernel<<<dim3(8, NB*NH), 256, SMEM_ATTN>>>();

    ln_kernel<<<NB * (NL/TL), 128>>>(q, gamma, beta, out);
}

// round 9
// speedup vs baseline: 1.6886x; 1.6886x over previous
#include <cuda_runtime.h>

#define NB 8
#define NC 512
#define NL 1024
#define NH 8
#define ND 64
#define GC 64
#define LTILE 128

typedef unsigned long long u64;
typedef unsigned int u32;

// ---------------- scratch (allocation-free rule) ---------------------------
// Q/K: tf32 hi/lo pair-packed [bh][row][k(8)][q4(4)] float2 {v(8k+q4), v(8k+q4+4)}
__device__ float2 g_q2h[NB*NH*NL*32];
__device__ float2 g_q2l[NB*NH*NL*32];
__device__ float2 g_k2h[NB*NH*NL*32];
__device__ float2 g_k2l[NB*NH*NL*32];
// V: tf32 hi only, [bh][d][gp(128)][j(4)] float2 {v(d, 8gp+j), v(d, 8gp+j+4)}
__device__ float2 g_v2 [NB*NH*64*512];
__device__ float  g_o  [NB*NL*NC];     // attention output, [b][l][c]

// ---------------- f32x2 helpers (conv) -------------------------------------
__device__ __forceinline__ u64 pk2(float lo, float hi) {
    u64 r; asm("mov.b64 %0, {%1, %2};" : "=l"(r) : "f"(lo), "f"(hi)); return r;
}
__device__ __forceinline__ void upk2(float& lo, float& hi, u64 v) {
    asm("mov.b64 {%0, %1}, %2;" : "=f"(lo), "=f"(hi) : "l"(v));
}
__device__ __forceinline__ u64 fma2(u64 a, u64 b, u64 c) {
    u64 d; asm("fma.rn.f32x2 %0, %1, %2, %3;" : "=l"(d) : "l"(a), "l"(b), "l"(c)); return d;
}

// ---------------- tensor helpers (legacy mma.sync on sm_103) ---------------
__device__ __forceinline__ float tf32hi(float x) {
    u32 r; asm("cvt.rna.tf32.f32 %0, %1;" : "=r"(r) : "f"(x));
    return __uint_as_float(r);
}
__device__ __forceinline__ void mma8(float d[4], const u32 a[4], u32 b0, u32 b1) {
    asm volatile("mma.sync.aligned.m16n8k8.row.col.f32.tf32.tf32.f32 "
        "{%0,%1,%2,%3}, {%4,%5,%6,%7}, {%8,%9}, {%0,%1,%2,%3};"
        : "+f"(d[0]), "+f"(d[1]), "+f"(d[2]), "+f"(d[3])
        : "r"(a[0]), "r"(a[1]), "r"(a[2]), "r"(a[3]), "r"(b0), "r"(b1));
}
__device__ __forceinline__ u32 smem_u32(const void* p) {
    u32 a; asm("{ .reg .u64 t; cvta.to.shared.u64 t, %1; cvt.u32.u64 %0, t; }"
               : "=r"(a) : "l"(p)); return a;
}

// ---------------------------------------------------------------------------
// Grouped Conv1d: f32x2 compute (unchanged); writer now emits tf32 hi/lo
// pair-packed layouts consumed directly by the attention kernel.
// which: 0 -> Q (scaled by 1/sqrt(8), hi+lo), 1 -> K (hi+lo), 2 -> V (hi only)
// ---------------------------------------------------------------------------
__global__ __launch_bounds__(256, 2)
void conv_kernel(const float* __restrict__ x, const float* __restrict__ w, int which)
{
    __shared__ __align__(16) float xs [GC][LTILE+2];
    __shared__ float xt2[GC][LTILE+1];

    int bg = blockIdx.y;
    int b  = bg >> 3, g = bg & 7;
    int lt = blockIdx.x * LTILE;
    int tid = threadIdx.x;

    const float* xg = x + (size_t)(b*NC + g*GC) * NL;
    for (int i = tid; i < GC*(LTILE+2); i += 256) {
        int ch = i / (LTILE+2);
        int lo = i - ch*(LTILE+2);
        int lp = lt - 1 + lo;
        lp = (lp < 0) ? 1 : ((lp >= NL) ? (2*NL - 2 - lp) : lp);  // reflect
        xs[ch][lo] = xg[ch*NL + lp];
    }
    __syncthreads();

    int c  = tid >> 2;
    int lq = tid & 3;
    const float* wc = w + (size_t)(g*GC + c) * 192;

    u64 acc2[4][4];
    #pragma unroll
    for (int rp = 0; rp < 4; ++rp)
        #pragma unroll
        for (int j = 0; j < 4; ++j) acc2[rp][j] = 0ull;

    #pragma unroll 4
    for (int i = 0; i < GC; ++i) {
        float w0 = wc[i*3+0], w1 = wc[i*3+1], w2 = wc[i*3+2];
        u64 w00 = pk2(w0, w0), w11 = pk2(w1, w1), w22 = pk2(w2, w2);
        #pragma unroll
        for (int rp = 0; rp < 4; ++rp) {
            int l0 = rp*32 + lq*8;
            float xr[10];
            #pragma unroll
            for (int r = 0; r < 10; ++r) xr[r] = xs[i][l0 + r];
            u64 E[5], O[4];
            #pragma unroll
            for (int j = 0; j < 5; ++j) E[j] = pk2(xr[2*j],   xr[2*j+1]);
            #pragma unroll
            for (int j = 0; j < 4; ++j) O[j] = pk2(xr[2*j+1], xr[2*j+2]);
            #pragma unroll
            for (int j = 0; j < 4; ++j) {
                acc2[rp][j] = fma2(w00, E[j],   acc2[rp][j]);
                acc2[rp][j] = fma2(w11, O[j],   acc2[rp][j]);
                acc2[rp][j] = fma2(w22, E[j+1], acc2[rp][j]);
            }
        }
    }

    if (which == 2) {
        // V: hi-only pair packing over l (pairs j, j+4 within each 8-chunk)
        float2* vh = g_v2 + (size_t)bg*64*512 + (size_t)c*512;
        #pragma unroll
        for (int rp = 0; rp < 4; ++rp) {
            int l0 = rp*32 + lq*8;
            float a0,a1,a2v,a3,a4,a5,a6,a7;
            upk2(a0,a1, acc2[rp][0]); upk2(a2v,a3, acc2[rp][1]);
            upk2(a4,a5, acc2[rp][2]); upk2(a6,a7, acc2[rp][3]);
            int gp = (lt + l0) >> 3;
            vh[gp*4+0] = make_float2(tf32hi(a0),  tf32hi(a4));
            vh[gp*4+1] = make_float2(tf32hi(a1),  tf32hi(a5));
            vh[gp*4+2] = make_float2(tf32hi(a2v), tf32hi(a6));
            vh[gp*4+3] = make_float2(tf32hi(a3),  tf32hi(a7));
        }
    } else {
        // Q/K: transpose via smem, then hi/lo pair-packed writes
        #pragma unroll
        for (int rp = 0; rp < 4; ++rp) {
            int l0 = rp*32 + lq*8;
            float a0,a1,a2v,a3,a4,a5,a6,a7;
            upk2(a0,a1, acc2[rp][0]); upk2(a2v,a3, acc2[rp][1]);
            upk2(a4,a5, acc2[rp][2]); upk2(a6,a7, acc2[rp][3]);
            xt2[c][l0+0]=a0; xt2[c][l0+1]=a1; xt2[c][l0+2]=a2v; xt2[c][l0+3]=a3;
            xt2[c][l0+4]=a4; xt2[c][l0+5]=a5; xt2[c][l0+6]=a6;  xt2[c][l0+7]=a7;
        }
        __syncthreads();
        float2* hi = (which==0 ? g_q2h : g_k2h) + (size_t)bg*NL*32;
        float2* lo = (which==0 ? g_q2l : g_k2l) + (size_t)bg*NL*32;
        float qs = (which == 0) ? 0.35355339059327373f : 1.0f;  // 1/sqrt(8)
        #pragma unroll
        for (int it = 0; it < 16; ++it) {
            int i = it*256 + tid;                 // 0..4095
            int l = i >> 5, kq = i & 31;
            int d0 = ((kq >> 2) << 3) + (kq & 3); // 8k + q4
            float f0 = xt2[d0  ][l] * qs;
            float f1 = xt2[d0+4][l] * qs;
            float h0 = tf32hi(f0), h1 = tf32hi(f1);
            size_t idx = (size_t)(lt + l)*32 + kq;
            hi[idx] = make_float2(h0, h1);
            lo[idx] = make_float2(f0 - h0, f1 - h1);
        }
    }
}

// ---------------------------------------------------------------------------
// Causal attention: mma.sync m16n8k8 tf32. QK x3-compensated, PV x2 (V hi only).
// Operands arrive pre-split/pre-packed from conv; staging = pure cp.async copy,
// double-buffered. B fragment = one LDS.64 per stream (pitch 36 f2, no conflicts).
// Block (qtile, bh): 256 thr = 8 warps; warp w owns rows [qt*128+w*16, +16).
// Key tiles of 64. exp-direct softmax (scores bounded; validated R3-R8).
// ---------------------------------------------------------------------------
#define KPIT2 36                       // float2 pitch per packed smem row
#define STG_BYTES (64*KPIT2*8)         // 18,432 per stream
#define STAGE_BYTES (3*STG_BYTES)      // Khi, Klo, Vhi
#define SMEM_ATTN (2*STAGE_BYTES)      // 110,592 (double buffer)

__global__ __launch_bounds__(256)
void attn_kernel()
{
    extern __shared__ __align__(16) char smraw[];
    u32 smb = smem_u32(smraw);

    int tid  = threadIdx.x;
    int w    = tid >> 5;
    int lane = tid & 31;
    int g    = lane >> 2;
    int q4   = lane & 3;
    int bh   = blockIdx.y;
    int qt   = 7 - blockIdx.x;         // heavy q-tiles first
    int row0 = qt * 128;

    // ---- Q fragments straight from gmem (pre-scaled, pre-split, pre-packed)
    const float2* qh = g_q2h + (size_t)bh*NL*32;
    const float2* ql = g_q2l + (size_t)bh*NL*32;
    int rbl = w*16 + g;
    u32 qAhi[8][4], qAlo[8][4];
    #pragma unroll
    for (int k = 0; k < 8; ++k) {
        float2 h0 = qh[(size_t)(row0+rbl  )*32 + k*4 + q4];
        float2 h1 = qh[(size_t)(row0+rbl+8)*32 + k*4 + q4];
        qAhi[k][0] = __float_as_uint(h0.x);
        qAhi[k][1] = __float_as_uint(h1.x);
        qAhi[k][2] = __float_as_uint(h0.y);
        qAhi[k][3] = __float_as_uint(h1.y);
        float2 l0v = ql[(size_t)(row0+rbl  )*32 + k*4 + q4];
        float2 l1v = ql[(size_t)(row0+rbl+8)*32 + k*4 + q4];
        qAlo[k][0] = __float_as_uint(l0v.x);
        qAlo[k][1] = __float_as_uint(l1v.x);
        qAlo[k][2] = __float_as_uint(l0v.y);
        qAlo[k][3] = __float_as_uint(l1v.y);
    }

    float oacc[8][4];
    #pragma unroll
    for (int n = 0; n < 8; ++n)
        #pragma unroll
        for (int e = 0; e < 4; ++e) oacc[n][e] = 0.f;
    float s0 = 0.f, s1 = 0.f;

    int rbase = row0 + rbl;
    int nkt   = 2*qt + 2;              // 64-key tiles
    int src0  = (lane & ~3) | (q4 >> 1);
    int src1  = src0 + 2;

    const char* khg = (const char*)(g_k2h + (size_t)bh*NL*32);
    const char* klg = (const char*)(g_k2l + (size_t)bh*NL*32);
    const char* vhg = (const char*)(g_v2  + (size_t)bh*64*512);

    // ---- stage: copy one tile (Khi, Klo, Vhi) into buffer via cp.async ----
    auto stage = [&](int kt, int buf) {
        u32 base = smb + buf*STAGE_BYTES;
        #pragma unroll
        for (int i = 0; i < 12; ++i) {
            int s   = i >> 2;                       // 0=Khi 1=Klo 2=Vhi
            int r   = ((i & 3) << 4) + (tid >> 4);  // row 0..63
            int c16 = tid & 15;
            u32 dst = base + s*STG_BYTES + r*288 + c16*16;
            const char* src;
            if      (s == 0) src = khg + ((size_t)(kt*64 + r)*32)*8 + c16*16;
            else if (s == 1) src = klg + ((size_t)(kt*64 + r)*32)*8 + c16*16;
            else             src = vhg + ((size_t)r*512 + kt*32)*8 + c16*16;
            asm volatile("cp.async.cg.shared.global [%0], [%1], 16;"
                         :: "r"(dst), "l"(src) : "memory");
        }
        asm volatile("cp.async.commit_group;" ::: "memory");
    };

    stage(0, 0);

    for (int kt = 0; kt < nkt; ++kt) {
        int buf = kt & 1;
        __syncthreads();               // compute(kt-1) fully done before reuse
        if (kt + 1 < nkt) {
            stage(kt + 1, (kt + 1) & 1);
            asm volatile("cp.async.wait_group 1;" ::: "memory");
        } else {
            asm volatile("cp.async.wait_group 0;" ::: "memory");
        }
        __syncthreads();

        const float2* Kh = (const float2*)(smraw + buf*STAGE_BYTES);
        const float2* Kl = (const float2*)(smraw + buf*STAGE_BYTES + STG_BYTES);
        const float2* Vh = (const float2*)(smraw + buf*STAGE_BYTES + 2*STG_BYTES);

        // ---- S = Q K^T (x3): B frag = 2 LDS.64 + 3 HMMA ----
        float sc[8][4];
        #pragma unroll
        for (int n = 0; n < 8; ++n)
            #pragma unroll
            for (int e = 0; e < 4; ++e) sc[n][e] = 0.f;

        #pragma unroll
        for (int k = 0; k < 8; ++k) {
            #pragma unroll
            for (int n = 0; n < 8; ++n) {
                int ro = (8*n + g)*KPIT2 + k*4 + q4;
                float2 bhp = Kh[ro];
                float2 blp = Kl[ro];
                u32 bh0 = __float_as_uint(bhp.x), bh1 = __float_as_uint(bhp.y);
                mma8(sc[n], qAhi[k], bh0, bh1);
                mma8(sc[n], qAlo[k], bh0, bh1);
                mma8(sc[n], qAhi[k],
                     __float_as_uint(blp.x), __float_as_uint(blp.y));
            }
        }

        // ---- softmax: exp-direct + causal mask ----
        #pragma unroll
        for (int n = 0; n < 8; ++n) {
            int cbase = kt*64 + 8*n + 2*q4;
            #pragma unroll
            for (int e = 0; e < 4; ++e) {
                int r = rbase + ((e >> 1) << 3);
                int c = cbase + (e & 1);
                float p = (c > r) ? 0.f : __expf(sc[n][e]);
                sc[n][e] = p;
                if (e < 2) s0 += p; else s1 += p;
            }
        }

        // ---- O += P V^T (x2: P hi/lo, V hi): 1 LDS.64 + 2 HMMA ----
        #pragma unroll
        for (int kk = 0; kk < 8; ++kk) {
            float v00 = __shfl_sync(0xffffffffu, sc[kk][0], src0);
            float v01 = __shfl_sync(0xffffffffu, sc[kk][1], src0);
            float v20 = __shfl_sync(0xffffffffu, sc[kk][2], src0);
            float v21 = __shfl_sync(0xffffffffu, sc[kk][3], src0);
            float w00 = __shfl_sync(0xffffffffu, sc[kk][0], src1);
            float w01 = __shfl_sync(0xffffffffu, sc[kk][1], src1);
            float w20 = __shfl_sync(0xffffffffu, sc[kk][2], src1);
            float w21 = __shfl_sync(0xffffffffu, sc[kk][3], src1);
            bool odd = (q4 & 1);
            float a[4];
            a[0] = odd ? v01 : v00;
            a[1] = odd ? v21 : v20;
            a[2] = odd ? w01 : w00;
            a[3] = odd ? w21 : w20;
            u32 pahi[4], palo[4];
            #pragma unroll
            for (int e = 0; e < 4; ++e) {
                float h = tf32hi(a[e]);
                pahi[e] = __float_as_uint(h);
                palo[e] = __float_as_uint(a[e] - h);
            }
            #pragma unroll
            for (int n = 0; n < 8; ++n) {
                float2 bv = Vh[(8*n + g)*KPIT2 + kk*4 + q4];
                u32 b0 = __float_as_uint(bv.x), b1 = __float_as_uint(bv.y);
                mma8(oacc[n], pahi, b0, b1);
                mma8(oacc[n], palo, b0, b1);
            }
        }
    }

    // ---- finalize: quad-reduce row sums, normalize, write ----
    s0 += __shfl_xor_sync(0xffffffffu, s0, 1);
    s0 += __shfl_xor_sync(0xffffffffu, s0, 2);
    s1 += __shfl_xor_sync(0xffffffffu, s1, 1);
    s1 += __shfl_xor_sync(0xffffffffu, s1, 2);
    float inv0 = 1.f / s0, inv1 = 1.f / s1;

    int b = bh >> 3, h = bh & 7;
    float* Ob0 = g_o + ((size_t)(b*NL + rbase    ))*NC + h*ND;
    float* Ob1 = g_o + ((size_t)(b*NL + rbase + 8))*NC + h*ND;
    #pragma unroll
    for (int n = 0; n < 8; ++n) {
        int d = 8*n + 2*q4;
        *(float2*)(Ob0 + d) = make_float2(oacc[n][0]*inv0, oacc[n][1]*inv0);
        *(float2*)(Ob1 + d) = make_float2(oacc[n][2]*inv1, oacc[n][3]*inv1);
    }
}

// ---------------------------------------------------------------------------
// Residual add + LayerNorm over channel, transposed-tile version (unchanged).
// ---------------------------------------------------------------------------
#define TL 16
__global__ __launch_bounds__(128)
void ln_kernel(const float* __restrict__ init, const float* __restrict__ gamma,
               const float* __restrict__ beta, float* __restrict__ y)
{
    __shared__ float xt[TL][NC + 4];

    int blk = blockIdx.x;
    int b   = blk >> 6;
    int lt  = (blk & 63) * TL;
    int tid = threadIdx.x;

    const float* ib = init + (size_t)b * NC * NL + lt;
    float*       yb = y    + (size_t)b * NC * NL + lt;

    for (int i = tid; i < NC * (TL/4); i += 128) {
        int c = i >> 2, j = i & 3;
        float4 v = *(const float4*)(ib + (size_t)c * NL + 4*j);
        xt[4*j+0][c] = v.x; xt[4*j+1][c] = v.y;
        xt[4*j+2][c] = v.z; xt[4*j+3][c] = v.w;
    }
    __syncthreads();

    int w = tid >> 5, lane = tid & 31;
    const float* ob_base = g_o + ((size_t)(b*NL + lt)) * NC;
    for (int r = w; r < TL; r += 4) {
        const float4* orow = (const float4*)(ob_base + (size_t)r * NC);
        float4 xv[4];
        float s1 = 0.f, s2 = 0.f;
        #pragma unroll
        for (int kk = 0; kk < 4; ++kk) {
            int c4 = lane + 32*kk;
            float4 ov = orow[c4];
            float4 iv = *(const float4*)(&xt[r][4*c4]);
            xv[kk] = make_float4(ov.x+iv.x, ov.y+iv.y, ov.z+iv.z, ov.w+iv.w);
            s1 += xv[kk].x + xv[kk].y + xv[kk].z + xv[kk].w;
            s2 += xv[kk].x*xv[kk].x + xv[kk].y*xv[kk].y
                + xv[kk].z*xv[kk].z + xv[kk].w*xv[kk].w;
        }
        #pragma unroll
        for (int off = 16; off; off >>= 1) {
            s1 += __shfl_xor_sync(0xffffffffu, s1, off);
            s2 += __shfl_xor_sync(0xffffffffu, s2, off);
        }
        float mu   = s1 * (1.f/512.f);
        float var  = s2 * (1.f/512.f) - mu*mu;
        float rstd = rsqrtf(var + 1e-5f);

        #pragma unroll
        for (int kk = 0; kk < 4; ++kk) {
            int c4 = lane + 32*kk;
            float4 gv = ((const float4*)gamma)[c4];
            float4 bv = ((const float4*)beta)[c4];
            float4 r4;
            r4.x = (xv[kk].x - mu)*rstd*gv.x + bv.x;
            r4.y = (xv[kk].y - mu)*rstd*gv.y + bv.y;
            r4.z = (xv[kk].z - mu)*rstd*gv.z + bv.z;
            r4.w = (xv[kk].w - mu)*rstd*gv.w + bv.w;
            *(float4*)(&xt[r][4*c4]) = r4;
        }
    }
    __syncthreads();

    for (int i = tid; i < NC * (TL/4); i += 128) {
        int c = i >> 2, j = i & 3;
        float4 v = make_float4(xt[4*j+0][c], xt[4*j+1][c],
                               xt[4*j+2][c], xt[4*j+3][c]);
        *(float4*)(yb + (size_t)c * NL + 4*j) = v;
    }
}

// ---------------------------------------------------------------------------
extern "C" void kernel_launch(void* const* d_in, const int* in_sizes, int n_in,
                              void* d_out, int out_size)
{
    const float* q     = (const float*)d_in[0];
    const float* k     = (const float*)d_in[1];
    // d_in[2] = mask — causal, handled analytically
    const float* wq    = (const float*)d_in[3];
    const float* wk    = (const float*)d_in[4];
    const float* wv    = (const float*)d_in[5];
    const float* gamma = (const float*)d_in[6];
    const float* beta  = (const float*)d_in[7];
    float* out = (float*)d_out;

    cudaFuncSetAttribute(attn_kernel,
                         cudaFuncAttributeMaxDynamicSharedMemorySize, SMEM_ATTN);

    dim3 cgrid(NL / LTILE, NB * NH);
    conv_kernel<<<cgrid, 256>>>(q, wq, 0);
    conv_kernel<<<cgrid, 256>>>(k, wk, 1);
    conv_kernel<<<cgrid, 256>>>(k, wv, 2);   // v = k

    attn_kernel<<<dim3(8, NB*NH), 256, SMEM_ATTN>>>();

    ln_kernel<<<NB * (NL/TL), 128>>>(q, gamma, beta, out);
}

// round 11
// speedup vs baseline: 2.1198x; 1.2553x over previous
#include <cuda_runtime.h>

#define NB 8
#define NC 512
#define NL 1024
#define NH 8
#define ND 64

typedef unsigned long long u64;
typedef unsigned int u32;

// ---------------- scratch (allocation-free rule) ---------------------------
// Q/K: tf32 hi/lo pair-packed [bh][row][k(8)][q4(4)] float2 {v(8k+q4), v(8k+q4+4)}
__device__ float2 g_q2h[NB*NH*NL*32];
__device__ float2 g_q2l[NB*NH*NL*32];
__device__ float2 g_k2h[NB*NH*NL*32];
__device__ float2 g_k2l[NB*NH*NL*32];
// V: tf32 hi only, [bh][d][gp(128)][j(4)] float2 {v(d, 8gp+j), v(d, 8gp+j+4)}
__device__ float2 g_v2 [NB*NH*64*512];
__device__ float  g_o  [NB*NL*NC];     // attention output, [b][l][c]
// weights pre-packed: [cv][g][t*64+c][36] f2 pairs over i {w(8k+q4), w(8k+q4+4)}
__device__ float2 g_wp_h[3*64*192*36];
__device__ float2 g_wp_l[3*64*192*36];

// ---------------- tensor helpers (legacy mma.sync on sm_103) ---------------
__device__ __forceinline__ float tf32hi(float x) {
    u32 r; asm("cvt.rna.tf32.f32 %0, %1;" : "=r"(r) : "f"(x));
    return __uint_as_float(r);
}
__device__ __forceinline__ void mma8(float d[4], const u32 a[4], u32 b0, u32 b1) {
    asm volatile("mma.sync.aligned.m16n8k8.row.col.f32.tf32.tf32.f32 "
        "{%0,%1,%2,%3}, {%4,%5,%6,%7}, {%8,%9}, {%0,%1,%2,%3};"
        : "+f"(d[0]), "+f"(d[1]), "+f"(d[2]), "+f"(d[3])
        : "r"(a[0]), "r"(a[1]), "r"(a[2]), "r"(a[3]), "r"(b0), "r"(b1));
}
__device__ __forceinline__ u32 smem_u32(const void* p) {
    u32 a; asm("{ .reg .u64 t; cvta.to.shared.u64 t, %1; cvt.u32.u64 %0, t; }"
               : "=r"(a) : "l"(p)); return a;
}

// ---------------------------------------------------------------------------
// pack_w: weights -> pair-packed tf32 hi/lo, [cv][g][t*64+c][36] f2.
// Q weights (cv=0) pre-scaled by 1/sqrt(8). grid (64, 3) x 256 threads.
// ---------------------------------------------------------------------------
__global__ void pack_w(const float* __restrict__ wq, const float* __restrict__ wk,
                       const float* __restrict__ wv)
{
    int g  = blockIdx.x;
    int cv = blockIdx.y;
    const float* w = (cv == 0) ? wq : (cv == 1) ? wk : wv;
    float s = (cv == 0) ? 0.35355339059327373f : 1.0f;

    int tid = threadIdx.x;
    #pragma unroll
    for (int it = 0; it < 24; ++it) {
        int u  = it*256 + tid;            // < 6144
        int r  = u >> 5;                  // t*64 + c
        int k4 = u & 31;
        int t  = r >> 6, c = r & 63;
        int i0 = ((k4 >> 2) << 3) | (k4 & 3);
        float v0 = w[(size_t)((g*64 + c)*64 + i0    )*3 + t] * s;
        float v1 = w[(size_t)((g*64 + c)*64 + i0 + 4)*3 + t] * s;
        float h0 = tf32hi(v0), h1 = tf32hi(v1);
        size_t base = (size_t)((cv*64 + g)*192 + r)*36 + k4;
        g_wp_h[base] = make_float2(h0, h1);
        g_wp_l[base] = make_float2(v0 - h0, v1 - h1);
    }
}

// ---------------------------------------------------------------------------
// conv_mma: grouped conv1d as tensor-core GEMM, out^T = X^T * W^T per (b,g,lt).
// M=128(l) x N=64(c) x K=192 ((t,i)); mma m16n8k8 tf32.
// cv=0(Q),1(K): x3-compensated; cv=2(V): x2 (w hi-only).
// Epilogue emits the exact R9 packed layouts consumed by attn (unchanged).
// grid (8 ltiles, 64 bg, 3 cv), 256 thr = 8 warps.
// ---------------------------------------------------------------------------
#define OFF_RAW 0                           // xs [64 i][134 f]   = 34,304 B
#define OFF_XH  34304                       // xp_hi [132][36] f2 = 38,016 B
#define OFF_XL  (OFF_XH + 38016)
#define OFF_WH  (OFF_XL + 38016)            // wp_hi [192][36] f2 = 55,296 B
#define OFF_WL  (OFF_WH + 55296)
#define SMEM_CONV (OFF_WL + 55296)          // 220,928 B

__global__ __launch_bounds__(256)
void conv_mma(const float* __restrict__ qin, const float* __restrict__ kin)
{
    extern __shared__ __align__(16) char sm[];
    u32 smb = smem_u32(sm);
    float*  xs = (float*) (sm + OFF_RAW);
    float*  oT = (float*) (sm + OFF_RAW);   // reused after GEMM
    float2* XH = (float2*)(sm + OFF_XH);
    float2* XL = (float2*)(sm + OFF_XL);
    float2* WH = (float2*)(sm + OFF_WH);
    float2* WL = (float2*)(sm + OFF_WL);

    int tid  = threadIdx.x;
    int w    = tid >> 5;
    int lane = tid & 31;
    int g    = lane >> 2;
    int q4   = lane & 3;
    int lt   = blockIdx.x * 128;
    int bg   = blockIdx.y;
    int cv   = blockIdx.z;
    int b    = bg >> 3, gr = bg & 7;

    const float* xin = (cv == 0) ? qin : kin;
    const float* xg  = xin + (size_t)(b*NC + gr*64) * NL;

    // ---- cp.async weights (pure copy; 288B row pitch) ----
    {
        const char* wsh = (const char*)g_wp_h + (size_t)(cv*64 + gr)*192*288;
        const char* wsl = (const char*)g_wp_l + (size_t)(cv*64 + gr)*192*288;
        #pragma unroll
        for (int it = 0; it < 14; ++it) {
            int u = it*256 + tid;
            if (u < 3456) {
                asm volatile("cp.async.cg.shared.global [%0], [%1], 16;"
                             :: "r"(smb + OFF_WH + u*16), "l"(wsh + (size_t)u*16) : "memory");
                if (cv != 2)
                    asm volatile("cp.async.cg.shared.global [%0], [%1], 16;"
                                 :: "r"(smb + OFF_WL + u*16), "l"(wsl + (size_t)u*16) : "memory");
            }
        }
        asm volatile("cp.async.commit_group;" ::: "memory");
    }

    // ---- stage raw x tile [64 i][132 r] (reflect pad), coalesced ----
    #pragma unroll
    for (int it = 0; it < 32; ++it) {
        int u = it*256 + tid;
        int i = u >> 7, r = u & 127;
        int l = lt - 1 + r;
        l = (l < 0) ? 1 : ((l >= NL) ? (2*NL - 2 - l) : l);
        xs[i*134 + r] = xg[(size_t)i*NL + l];
    }
    {   // tail rows 128..131
        int i = tid >> 2, r = 128 + (tid & 3);
        int l = lt - 1 + r;
        l = (l < 0) ? 1 : ((l >= NL) ? (2*NL - 2 - l) : l);
        xs[i*134 + r] = xg[(size_t)i*NL + l];
    }
    __syncthreads();

    // ---- transpose + tf32 split into pair layout xp[r][k4] ----
    // float index fs within a row = 8k + 2q + h  (pair {i=8k+q, i=8k+q+4})
    #pragma unroll
    for (int it = 0; it < 33; ++it) {
        int u = it*256 + tid;             // < 8448 = 132*64
        int r = u >> 6, fs = u & 63;
        int k = fs >> 3, q = (fs >> 1) & 3, h = fs & 1;   // FIXED: fs>>3
        int i = 8*k + q + 4*h;
        float v = xs[i*134 + r];
        float hv = tf32hi(v);
        ((float*)XH)[r*72 + fs] = hv;
        ((float*)XL)[r*72 + fs] = v - hv;
    }
    asm volatile("cp.async.wait_group 0;" ::: "memory");
    __syncthreads();

    // ---- GEMM: warp w owns l-strip rows [w*16, +16) ----
    float oacc[8][4];
    #pragma unroll
    for (int n = 0; n < 8; ++n)
        #pragma unroll
        for (int e = 0; e < 4; ++e) oacc[n][e] = 0.f;

    int base = w*16 + g;
    #pragma unroll
    for (int t = 0; t < 3; ++t) {
        #pragma unroll
        for (int k = 0; k < 8; ++k) {
            float2 ah0 = XH[(base + t    )*36 + k*4 + q4];
            float2 ah1 = XH[(base + t + 8)*36 + k*4 + q4];
            float2 al0 = XL[(base + t    )*36 + k*4 + q4];
            float2 al1 = XL[(base + t + 8)*36 + k*4 + q4];
            u32 ahi[4] = {__float_as_uint(ah0.x), __float_as_uint(ah1.x),
                          __float_as_uint(ah0.y), __float_as_uint(ah1.y)};
            u32 alo[4] = {__float_as_uint(al0.x), __float_as_uint(al1.x),
                          __float_as_uint(al0.y), __float_as_uint(al1.y)};
            #pragma unroll
            for (int n = 0; n < 8; ++n) {
                int ro = (t*64 + 8*n + g)*36 + k*4 + q4;
                float2 bh = WH[ro];
                u32 b0 = __float_as_uint(bh.x), b1 = __float_as_uint(bh.y);
                mma8(oacc[n], ahi, b0, b1);
                mma8(oacc[n], alo, b0, b1);
                if (cv != 2) {
                    float2 bl = WL[ro];
                    mma8(oacc[n], ahi,
                         __float_as_uint(bl.x), __float_as_uint(bl.y));
                }
            }
        }
    }

    // ---- store accumulators to smem oT[c][134 + l] ----
    {
        int l0 = base, l1 = base + 8;
        #pragma unroll
        for (int n = 0; n < 8; ++n) {
            int c0 = 8*n + 2*q4;
            oT[(c0    )*134 + l0] = oacc[n][0];
            oT[(c0 + 1)*134 + l0] = oacc[n][1];
            oT[(c0    )*134 + l1] = oacc[n][2];
            oT[(c0 + 1)*134 + l1] = oacc[n][3];
        }
    }
    __syncthreads();

    // ---- pack epilogue (R9 layouts) ----
    if (cv != 2) {
        float2* hi = ((cv == 0) ? g_q2h : g_k2h) + (size_t)bg*NL*32;
        float2* lo = ((cv == 0) ? g_q2l : g_k2l) + (size_t)bg*NL*32;
        #pragma unroll
        for (int it = 0; it < 16; ++it) {
            int u  = it*256 + tid;        // < 4096
            int l  = u >> 5, kq = u & 31;
            int d0 = ((kq >> 2) << 3) | (kq & 3);
            float f0 = oT[(d0    )*134 + l];
            float f1 = oT[(d0 + 4)*134 + l];
            float h0 = tf32hi(f0), h1 = tf32hi(f1);
            size_t idx = (size_t)(lt + l)*32 + kq;
            hi[idx] = make_float2(h0, h1);
            lo[idx] = make_float2(f0 - h0, f1 - h1);
        }
    } else {
        float2* vh = g_v2 + (size_t)bg*64*512;
        #pragma unroll
        for (int it = 0; it < 16; ++it) {
            int u  = it*256 + tid;        // < 4096
            int c  = u >> 6;
            int gp = (u >> 2) & 15, j = u & 3;
            float v0 = oT[c*134 + gp*8 + j];
            float v1 = oT[c*134 + gp*8 + j + 4];
            vh[(size_t)c*512 + ((lt >> 3) + gp)*4 + j] =
                make_float2(tf32hi(v0), tf32hi(v1));
        }
    }
}

// ---------------------------------------------------------------------------
// Causal attention (R9, unchanged): mma.sync tf32, QK x3 / PV x2,
// producer-packed operands, cp.async double-buffered K/V staging.
// ---------------------------------------------------------------------------
#define KPIT2 36
#define STG_BYTES (64*KPIT2*8)
#define STAGE_BYTES (3*STG_BYTES)
#define SMEM_ATTN (2*STAGE_BYTES)

__global__ __launch_bounds__(256)
void attn_kernel()
{
    extern __shared__ __align__(16) char smraw[];
    u32 smb = smem_u32(smraw);

    int tid  = threadIdx.x;
    int w    = tid >> 5;
    int lane = tid & 31;
    int g    = lane >> 2;
    int q4   = lane & 3;
    int bh   = blockIdx.y;
    int qt   = 7 - blockIdx.x;
    int row0 = qt * 128;

    const float2* qh = g_q2h + (size_t)bh*NL*32;
    const float2* ql = g_q2l + (size_t)bh*NL*32;
    int rbl = w*16 + g;
    u32 qAhi[8][4], qAlo[8][4];
    #pragma unroll
    for (int k = 0; k < 8; ++k) {
        float2 h0 = qh[(size_t)(row0+rbl  )*32 + k*4 + q4];
        float2 h1 = qh[(size_t)(row0+rbl+8)*32 + k*4 + q4];
        qAhi[k][0] = __float_as_uint(h0.x);
        qAhi[k][1] = __float_as_uint(h1.x);
        qAhi[k][2] = __float_as_uint(h0.y);
        qAhi[k][3] = __float_as_uint(h1.y);
        float2 l0v = ql[(size_t)(row0+rbl  )*32 + k*4 + q4];
        float2 l1v = ql[(size_t)(row0+rbl+8)*32 + k*4 + q4];
        qAlo[k][0] = __float_as_uint(l0v.x);
        qAlo[k][1] = __float_as_uint(l1v.x);
        qAlo[k][2] = __float_as_uint(l0v.y);
        qAlo[k][3] = __float_as_uint(l1v.y);
    }

    float oacc[8][4];
    #pragma unroll
    for (int n = 0; n < 8; ++n)
        #pragma unroll
        for (int e = 0; e < 4; ++e) oacc[n][e] = 0.f;
    float s0 = 0.f, s1 = 0.f;

    int rbase = row0 + rbl;
    int nkt   = 2*qt + 2;
    int src0  = (lane & ~3) | (q4 >> 1);
    int src1  = src0 + 2;

    const char* khg = (const char*)(g_k2h + (size_t)bh*NL*32);
    const char* klg = (const char*)(g_k2l + (size_t)bh*NL*32);
    const char* vhg = (const char*)(g_v2  + (size_t)bh*64*512);

    auto stage = [&](int kt, int buf) {
        u32 base = smb + buf*STAGE_BYTES;
        #pragma unroll
        for (int i = 0; i < 12; ++i) {
            int s   = i >> 2;
            int r   = ((i & 3) << 4) + (tid >> 4);
            int c16 = tid & 15;
            u32 dst = base + s*STG_BYTES + r*288 + c16*16;
            const char* src;
            if      (s == 0) src = khg + ((size_t)(kt*64 + r)*32)*8 + c16*16;
            else if (s == 1) src = klg + ((size_t)(kt*64 + r)*32)*8 + c16*16;
            else             src = vhg + ((size_t)r*512 + kt*32)*8 + c16*16;
            asm volatile("cp.async.cg.shared.global [%0], [%1], 16;"
                         :: "r"(dst), "l"(src) : "memory");
        }
        asm volatile("cp.async.commit_group;" ::: "memory");
    };

    stage(0, 0);

    for (int kt = 0; kt < nkt; ++kt) {
        int buf = kt & 1;
        __syncthreads();
        if (kt + 1 < nkt) {
            stage(kt + 1, (kt + 1) & 1);
            asm volatile("cp.async.wait_group 1;" ::: "memory");
        } else {
            asm volatile("cp.async.wait_group 0;" ::: "memory");
        }
        __syncthreads();

        const float2* Kh = (const float2*)(smraw + buf*STAGE_BYTES);
        const float2* Kl = (const float2*)(smraw + buf*STAGE_BYTES + STG_BYTES);
        const float2* Vh = (const float2*)(smraw + buf*STAGE_BYTES + 2*STG_BYTES);

        float sc[8][4];
        #pragma unroll
        for (int n = 0; n < 8; ++n)
            #pragma unroll
            for (int e = 0; e < 4; ++e) sc[n][e] = 0.f;

        #pragma unroll
        for (int k = 0; k < 8; ++k) {
            #pragma unroll
            for (int n = 0; n < 8; ++n) {
                int ro = (8*n + g)*KPIT2 + k*4 + q4;
                float2 bhp = Kh[ro];
                float2 blp = Kl[ro];
                u32 bh0 = __float_as_uint(bhp.x), bh1 = __float_as_uint(bhp.y);
                mma8(sc[n], qAhi[k], bh0, bh1);
                mma8(sc[n], qAlo[k], bh0, bh1);
                mma8(sc[n], qAhi[k],
                     __float_as_uint(blp.x), __float_as_uint(blp.y));
            }
        }

        #pragma unroll
        for (int n = 0; n < 8; ++n) {
            int cbase = kt*64 + 8*n + 2*q4;
            #pragma unroll
            for (int e = 0; e < 4; ++e) {
                int r = rbase + ((e >> 1) << 3);
                int c = cbase + (e & 1);
                float p = (c > r) ? 0.f : __expf(sc[n][e]);
                sc[n][e] = p;
                if (e < 2) s0 += p; else s1 += p;
            }
        }

        #pragma unroll
        for (int kk = 0; kk < 8; ++kk) {
            float v00 = __shfl_sync(0xffffffffu, sc[kk][0], src0);
            float v01 = __shfl_sync(0xffffffffu, sc[kk][1], src0);
            float v20 = __shfl_sync(0xffffffffu, sc[kk][2], src0);
            float v21 = __shfl_sync(0xffffffffu, sc[kk][3], src0);
            float w00 = __shfl_sync(0xffffffffu, sc[kk][0], src1);
            float w01 = __shfl_sync(0xffffffffu, sc[kk][1], src1);
            float w20 = __shfl_sync(0xffffffffu, sc[kk][2], src1);
            float w21 = __shfl_sync(0xffffffffu, sc[kk][3], src1);
            bool odd = (q4 & 1);
            float a[4];
            a[0] = odd ? v01 : v00;
            a[1] = odd ? v21 : v20;
            a[2] = odd ? w01 : w00;
            a[3] = odd ? w21 : w20;
            u32 pahi[4], palo[4];
            #pragma unroll
            for (int e = 0; e < 4; ++e) {
                float h = tf32hi(a[e]);
                pahi[e] = __float_as_uint(h);
                palo[e] = __float_as_uint(a[e] - h);
            }
            #pragma unroll
            for (int n = 0; n < 8; ++n) {
                float2 bv = Vh[(8*n + g)*KPIT2 + kk*4 + q4];
                u32 b0 = __float_as_uint(bv.x), b1 = __float_as_uint(bv.y);
                mma8(oacc[n], pahi, b0, b1);
                mma8(oacc[n], palo, b0, b1);
            }
        }
    }

    s0 += __shfl_xor_sync(0xffffffffu, s0, 1);
    s0 += __shfl_xor_sync(0xffffffffu, s0, 2);
    s1 += __shfl_xor_sync(0xffffffffu, s1, 1);
    s1 += __shfl_xor_sync(0xffffffffu, s1, 2);
    float inv0 = 1.f / s0, inv1 = 1.f / s1;

    int b = bh >> 3, h = bh & 7;
    float* Ob0 = g_o + ((size_t)(b*NL + rbase    ))*NC + h*ND;
    float* Ob1 = g_o + ((size_t)(b*NL + rbase + 8))*NC + h*ND;
    #pragma unroll
    for (int n = 0; n < 8; ++n) {
        int d = 8*n + 2*q4;
        *(float2*)(Ob0 + d) = make_float2(oacc[n][0]*inv0, oacc[n][1]*inv0);
        *(float2*)(Ob1 + d) = make_float2(oacc[n][2]*inv1, oacc[n][3]*inv1);
    }
}

// ---------------------------------------------------------------------------
// Residual add + LayerNorm over channel, transposed-tile version (unchanged).
// ---------------------------------------------------------------------------
#define TL 16
__global__ __launch_bounds__(128)
void ln_kernel(const float* __restrict__ init, const float* __restrict__ gamma,
               const float* __restrict__ beta, float* __restrict__ y)
{
    __shared__ float xt[TL][NC + 4];

    int blk = blockIdx.x;
    int b   = blk >> 6;
    int lt  = (blk & 63) * TL;
    int tid = threadIdx.x;

    const float* ib = init + (size_t)b * NC * NL + lt;
    float*       yb = y    + (size_t)b * NC * NL + lt;

    for (int i = tid; i < NC * (TL/4); i += 128) {
        int c = i >> 2, j = i & 3;
        float4 v = *(const float4*)(ib + (size_t)c * NL + 4*j);
        xt[4*j+0][c] = v.x; xt[4*j+1][c] = v.y;
        xt[4*j+2][c] = v.z; xt[4*j+3][c] = v.w;
    }
    __syncthreads();

    int w = tid >> 5, lane = tid & 31;
    const float* ob_base = g_o + ((size_t)(b*NL + lt)) * NC;
    for (int r = w; r < TL; r += 4) {
        const float4* orow = (const float4*)(ob_base + (size_t)r * NC);
        float4 xv[4];
        float s1 = 0.f, s2 = 0.f;
        #pragma unroll
        for (int kk = 0; kk < 4; ++kk) {
            int c4 = lane + 32*kk;
            float4 ov = orow[c4];
            float4 iv = *(const float4*)(&xt[r][4*c4]);
            xv[kk] = make_float4(ov.x+iv.x, ov.y+iv.y, ov.z+iv.z, ov.w+iv.w);
            s1 += xv[kk].x + xv[kk].y + xv[kk].z + xv[kk].w;
            s2 += xv[kk].x*xv[kk].x + xv[kk].y*xv[kk].y
                + xv[kk].z*xv[kk].z + xv[kk].w*xv[kk].w;
        }
        #pragma unroll
        for (int off = 16; off; off >>= 1) {
            s1 += __shfl_xor_sync(0xffffffffu, s1, off);
            s2 += __shfl_xor_sync(0xffffffffu, s2, off);
        }
        float mu   = s1 * (1.f/512.f);
        float var  = s2 * (1.f/512.f) - mu*mu;
        float rstd = rsqrtf(var + 1e-5f);

        #pragma unroll
        for (int kk = 0; kk < 4; ++kk) {
            int c4 = lane + 32*kk;
            float4 gv = ((const float4*)gamma)[c4];
            float4 bv = ((const float4*)beta)[c4];
            float4 r4;
            r4.x = (xv[kk].x - mu)*rstd*gv.x + bv.x;
            r4.y = (xv[kk].y - mu)*rstd*gv.y + bv.y;
            r4.z = (xv[kk].z - mu)*rstd*gv.z + bv.z;
            r4.w = (xv[kk].w - mu)*rstd*gv.w + bv.w;
            *(float4*)(&xt[r][4*c4]) = r4;
        }
    }
    __syncthreads();

    for (int i = tid; i < NC * (TL/4); i += 128) {
        int c = i >> 2, j = i & 3;
        float4 v = make_float4(xt[4*j+0][c], xt[4*j+1][c],
                               xt[4*j+2][c], xt[4*j+3][c]);
        *(float4*)(yb + (size_t)c * NL + 4*j) = v;
    }
}

// ---------------------------------------------------------------------------
extern "C" void kernel_launch(void* const* d_in, const int* in_sizes, int n_in,
                              void* d_out, int out_size)
{
    const float* q     = (const float*)d_in[0];
    const float* k     = (const float*)d_in[1];
    // d_in[2] = mask — causal, handled analytically
    const float* wq    = (const float*)d_in[3];
    const float* wk    = (const float*)d_in[4];
    const float* wv    = (const float*)d_in[5];
    const float* gamma = (const float*)d_in[6];
    const float* beta  = (const float*)d_in[7];
    float* out = (float*)d_out;

    cudaFuncSetAttribute(conv_mma,
                         cudaFuncAttributeMaxDynamicSharedMemorySize, SMEM_CONV);
    cudaFuncSetAttribute(attn_kernel,
                         cudaFuncAttributeMaxDynamicSharedMemorySize, SMEM_ATTN);

    pack_w<<<dim3(64, 3), 256>>>(wq, wk, wv);
    conv_mma<<<dim3(8, 64, 3), 256, SMEM_CONV>>>(q, k);
    attn_kernel<<<dim3(8, NB*NH), 256, SMEM_ATTN>>>();
    ln_kernel<<<NB * (NL/TL), 128>>>(q, gamma, beta, out);
}